// round 4
// baseline (speedup 1.0000x reference)
#include <cuda_runtime.h>
#include <cstdint>

#define T_STEPS 1000
#define BATCH   256
#define NIN     128
#define NHID    512
#define NOUT    128

#define NBLK 128
#define NTHR 512
#define BT 16      // batch rows per CTA
#define HT 64      // hidden cols per CTA
#define KTOT 640   // 512 recurrent + 128 input, unified GEMM K

#define WU_STRIDE 68   // floats per weight row (k-major), 4-float aligned, bank-spread
#define SS_STRIDE 20   // floats per s/x row (k-major), 4-float aligned, bank-spread

// shared-memory float offsets
#define OFF_WU 0
#define OFF_SS (KTOT*WU_STRIDE)              // 43520
#define OFF_SC (OFF_SS + KTOT*SS_STRIDE)     // 56320
#define SMEM_FLOATS (OFF_SC + BT*HT)         // 57344
#define SMEM_BYTES (SMEM_FLOATS*4)           // 229376 bytes (<= 227KB limit)

// s state rings (2 slots each) — L2-resident, .cg accessed only
__device__ float    g_s_ring [2*BATCH*NHID];   // b-major  [slot][b][h]
__device__ float    g_s_ringT[2*NHID*BATCH];   // k-major  [slot][h][b]
__device__ unsigned g_count = 0;
__device__ unsigned g_gen   = 0;

typedef unsigned long long u64;

__device__ __forceinline__ void ffma2(u64& d, u64 a, u64 b) {
  asm("fma.rn.f32x2 %0, %1, %2, %0;" : "+l"(d) : "l"(a), "l"(b));
}
__device__ __forceinline__ u64 bcast2(float s) {
  u64 r; asm("mov.b64 %0, {%1, %1};" : "=l"(r) : "f"(s)); return r;
}
__device__ __forceinline__ float2 unpack2(u64 p) {
  float2 f; asm("mov.b64 {%0, %1}, %2;" : "=f"(f.x), "=f"(f.y) : "l"(p)); return f;
}

__device__ __forceinline__ void grid_barrier() {
  __syncthreads();
  if (threadIdx.x == 0) {
    asm volatile("fence.acq_rel.gpu;" ::: "memory");   // release our s stores
    unsigned my = *((volatile unsigned*)&g_gen);
    if (atomicAdd(&g_count, 1u) == (unsigned)(NBLK - 1)) {
      atomicExch(&g_count, 0u);
      asm volatile("fence.acq_rel.gpu;" ::: "memory");
      atomicExch(&g_gen, my + 1u);
    } else {
      while (*((volatile unsigned*)&g_gen) == my) { }
    }
    asm volatile("fence.acq_rel.gpu;" ::: "memory");   // acquire
  }
  __syncthreads();
}

__global__ void __launch_bounds__(NTHR, 1)
bnn_kernel(const float* __restrict__ x,     // [T, B, NIN]
           const float* __restrict__ W_in,  // [NHID, NIN]
           const float* __restrict__ b_in,  // [NHID]
           const float* __restrict__ W_rec, // [NHID, NHID]
           const float* __restrict__ W_out, // [NOUT, NHID]
           const float* __restrict__ b_out, // [NOUT]
           float* __restrict__ out)         // [T, B, NOUT]
{
  extern __shared__ float sm[];
  float* wu  = sm + OFF_WU;   // [k=640][68]: unified weights, wu[k][hl] = W[h0+hl][k]
  float* ss  = sm + OFF_SS;   // [k=640][20]: k-major s (rows 0-511) + x (rows 512-639)
  float* scr = sm + OFF_SC;   // [1024]: reduction scratch / y buffer

  const int tid   = threadIdx.x;
  const int blk   = blockIdx.x;
  const int btile = blk >> 3;            // 16 b-tiles
  const int htile = blk & 7;             // 8  h-tiles
  const int b0 = btile * BT;
  const int h0 = htile * HT;

  // ---- prologue: weights into SMEM k-major (once for all 1000 steps) ----
  for (int i = tid; i < NHID*HT; i += NTHR) {
    int hl = i >> 9, k = i & 511;
    wu[k*WU_STRIDE + hl] = W_rec[(size_t)(h0 + hl)*NHID + k];
  }
  for (int i = tid; i < NIN*HT; i += NTHR) {
    int hl = i >> 7, k = i & 127;
    wu[(NHID + k)*WU_STRIDE + hl] = W_in[(size_t)(h0 + hl)*NIN + k];
  }
  // zero ss (s[-1]=0, pads), stage x[0] transposed
  for (int i = tid; i < KTOT*(SS_STRIDE/4); i += NTHR)
    ((float4*)ss)[i] = make_float4(0.f, 0.f, 0.f, 0.f);
  __syncthreads();
  for (int j = 0; j < 4; ++j) {
    int g = j*NTHR + tid;                // 0..2047
    int c = g & 127, bl = g >> 7;
    ss[(NHID + c)*SS_STRIDE + bl] = __ldg(x + (size_t)(b0 + bl)*NIN + c);
  }
  __syncthreads();

  // ---- GEMM mapping: lane = ksl(2b) | hq(1b) | bq(2b); warp = hgroup x wks ----
  const int lane = tid & 31;
  const int warp = tid >> 5;
  const int ksl  = lane & 3;             // in-warp k-slice (4)
  const int hq   = (lane >> 2) & 1;      // h-quad within 8h group
  const int bq   = lane >> 3;            // b-quad (4)
  const int hgroup = warp >> 1;          // 8 groups of 8 h
  const int wks  = warp & 1;             // cross-warp k-split (2)
  const int k0   = (wks*4 + ksl) * 80;   // 8 slices x 80 k

  const float4*     sp4 = (const float4*)ss + (size_t)k0*(SS_STRIDE/4) + bq;
  const ulonglong2* wp2 = (const ulonglong2*)wu + (size_t)k0*(WU_STRIDE/4)
                          + hgroup*2 + hq;

  // ---- update/publish mapping: thread owns (b = tid>>5, h-pair = tid&31) ----
  const int ub = tid >> 5;
  const int um = tid & 31;
  const float2 bin = *((const float2*)(b_in + h0) + um);

  // ---- readout mapping: warp = batch row, lanes: 16 o x 2 kh ----
  const int ob = warp;
  const int o  = htile * 16 + (lane & 15);
  const int kh = lane >> 4;
  const float bo = b_out[o];
  const float4* wo = (const float4*)(W_out + (size_t)o * NHID);

  float2 v  = make_float2(0.f, 0.f);
  float2 a0 = make_float2(0.f, 0.f);
  float2 a1 = make_float2(0.f, 0.f);
  float2 sp = make_float2(0.f, 0.f);

  for (int t = 0; t < T_STEPS; ++t) {
    // ---- GEMM: 4b x 4h outer product per thread over this lane's 80 k ----
    u64 acc[4][2] = {{0,0},{0,0},{0,0},{0,0}};
    #pragma unroll 4
    for (int r = 0; r < 80; ++r) {
      float4     sv = sp4[r*(SS_STRIDE/4)];
      ulonglong2 wv = wp2[r*(WU_STRIDE/4)];
      u64 s0 = bcast2(sv.x), s1 = bcast2(sv.y);
      u64 s2 = bcast2(sv.z), s3 = bcast2(sv.w);
      ffma2(acc[0][0], s0, wv.x); ffma2(acc[0][1], s0, wv.y);
      ffma2(acc[1][0], s1, wv.x); ffma2(acc[1][1], s1, wv.y);
      ffma2(acc[2][0], s2, wv.x); ffma2(acc[2][1], s2, wv.y);
      ffma2(acc[3][0], s3, wv.x); ffma2(acc[3][1], s3, wv.y);
    }
    // in-warp reduction over ksl (lane bits 0-1)
    float af[4][4];
    #pragma unroll
    for (int bi = 0; bi < 4; ++bi) {
      float2 lo = unpack2(acc[bi][0]), hi = unpack2(acc[bi][1]);
      af[bi][0] = lo.x; af[bi][1] = lo.y; af[bi][2] = hi.x; af[bi][3] = hi.y;
    }
    #pragma unroll
    for (int bi = 0; bi < 4; ++bi)
      #pragma unroll
      for (int c = 0; c < 4; ++c) {
        af[bi][c] += __shfl_xor_sync(0xffffffffu, af[bi][c], 1);
        af[bi][c] += __shfl_xor_sync(0xffffffffu, af[bi][c], 2);
      }

    // cross-warp (wks) 2-way reduction through 4KB scratch
    float4* A4 = (float4*)scr;
    if (wks == 1 && ksl == 0) {
      #pragma unroll
      for (int bi = 0; bi < 4; ++bi)
        A4[hgroup*32 + (4*bq + bi)*2 + hq] =
            make_float4(af[bi][0], af[bi][1], af[bi][2], af[bi][3]);
    }
    __syncthreads();
    float4 part[4];
    if (wks == 0 && ksl == 0) {
      #pragma unroll
      for (int bi = 0; bi < 4; ++bi)
        part[bi] = A4[hgroup*32 + (4*bq + bi)*2 + hq];
    }
    __syncthreads();
    if (wks == 0 && ksl == 0) {
      #pragma unroll
      for (int bi = 0; bi < 4; ++bi)
        A4[(4*bq + bi)*16 + hgroup*2 + hq] =
            make_float4(af[bi][0] + part[bi].x, af[bi][1] + part[bi].y,
                        af[bi][2] + part[bi].z, af[bi][3] + part[bi].w);
    }
    __syncthreads();

    // ---- GLIFR update: thread owns 2 outputs (b=ub, h=h0+2um..+1) ----
    {
      float2 yb = ((const float2*)scr)[ub*32 + um];
      #define UPD(i) { \
        float y  = 0.5f*(yb.i + bin.i); \
        a0.i = fmaf(a0.i,  0.85f, -0.05f*sp.i); \
        a1.i = fmaf(a1.i, -0.5f,  -0.05f*sp.i); \
        float it = y + a0.i + a1.i + 700.0f; \
        v.i  = v.i*0.99f*(1.0f - 0.05f*sp.i) + 0.00101953125f*it; \
        sp.i = 20.0f / (1.0f + __expf(-v.i*0.02f)); }
      UPD(x); UPD(y);
      #undef UPD

      const int slot = t & 1;
      const int gb = b0 + ub, gh = h0 + 2*um;
      __stcg((float2*)(g_s_ring + (size_t)slot*BATCH*NHID + (size_t)gb*NHID + gh), sp);
      float* rT = g_s_ringT + (size_t)slot*NHID*BATCH;
      __stcg(rT + (size_t)gh*BATCH + gb, sp.x);
      __stcg(rT + (size_t)(gh+1)*BATCH + gb, sp.y);
    }

    grid_barrier();

    const int slot = t & 1;

    // ---- readout: out[t] = s[t] @ W_out^T + b_out (ring b-major, via L2) ----
    {
      const float4* rb4 = (const float4*)(g_s_ring + (size_t)slot*BATCH*NHID
                                          + (size_t)(b0 + ob)*NHID);
      float oa = 0.f, obacc = 0.f;
      #pragma unroll 8
      for (int i = 0; i < 32; ++i) {
        int k4 = 4*i + 2*kh;
        float4 sv0 = __ldcg(rb4 + k4);
        float4 wv0 = __ldg(wo + k4);
        float4 sv1 = __ldcg(rb4 + k4 + 1);
        float4 wv1 = __ldg(wo + k4 + 1);
        oa    = fmaf(sv0.x, wv0.x, fmaf(sv0.y, wv0.y,
                fmaf(sv0.z, wv0.z, fmaf(sv0.w, wv0.w, oa))));
        obacc = fmaf(sv1.x, wv1.x, fmaf(sv1.y, wv1.y,
                fmaf(sv1.z, wv1.z, fmaf(sv1.w, wv1.w, obacc))));
      }
      float r = oa + obacc;
      r += __shfl_xor_sync(0xffffffffu, r, 16);
      if (kh == 0)
        out[(size_t)t*BATCH*NOUT + (size_t)(b0 + ob)*NOUT + o] = r + bo;
    }

    // ---- restage: s[t] (k-major ring) -> ss rows 0-511; x[t+1] -> rows 512+ ----
    {
      const float* rT = g_s_ringT + (size_t)slot*NHID*BATCH;
      #pragma unroll
      for (int j = 0; j < 4; ++j) {
        int g = j*NTHR + tid;            // 0..2047
        int k = g >> 2, bq4 = (g & 3)*4;
        float4 vv = __ldcg((const float4*)(rT + (size_t)k*BATCH + b0 + bq4));
        *(float4*)(ss + k*SS_STRIDE + bq4) = vv;
      }
      int tn = (t + 1 < T_STEPS) ? t + 1 : t;
      const float* xr = x + (size_t)tn*BATCH*NIN;
      #pragma unroll
      for (int j = 0; j < 4; ++j) {
        int g = j*NTHR + tid;            // 0..2047
        int c = g & 127, bl = g >> 7;
        ss[(NHID + c)*SS_STRIDE + bl] = __ldg(xr + (size_t)(b0 + bl)*NIN + c);
      }
    }
    __syncthreads();
  }
}

extern "C" void kernel_launch(void* const* d_in, const int* in_sizes, int n_in,
                              void* d_out, int out_size) {
  const float* x     = (const float*)d_in[0];
  const float* W_in  = (const float*)d_in[1];
  const float* b_in  = (const float*)d_in[2];
  const float* W_rec = (const float*)d_in[3];
  const float* W_out = (const float*)d_in[4];
  const float* b_out = (const float*)d_in[5];
  float* out = (float*)d_out;

  cudaFuncSetAttribute(bnn_kernel,
                       cudaFuncAttributeMaxDynamicSharedMemorySize, SMEM_BYTES);
  bnn_kernel<<<NBLK, NTHR, SMEM_BYTES>>>(x, W_in, b_in, W_rec, W_out, b_out, out);
}

// round 5
// speedup vs baseline: 1.3453x; 1.3453x over previous
#include <cuda_runtime.h>
#include <cstdint>

#define T_STEPS 1000
#define BATCH   256
#define NIN     128
#define NHID    512
#define NOUT    128

#define NBLK 128
#define NTHR 512
#define BT 16      // batch rows per CTA
#define HT 64      // hidden cols per CTA

#define SS_STRIDE 20    // floats per k-row of s/x (16 b + 4 pad)
#define SB_STRIDE 520   // floats per b-row of s (512 + 8 pad)

// shared float offsets
#define OFF_SS 0
#define OFF_SB (640*SS_STRIDE)            // 12800
#define OFF_ST (OFF_SB + BT*SB_STRIDE)    // 21120 (byte offset %8 == 0)
#define SMEM_FLOATS (OFF_ST + 4*512*2)    // + 4096 = 25216
#define SMEM_BYTES (SMEM_FLOATS*4)        // 100864 B

// L2-resident state rings (2 slots), accessed only via .cg
__device__ float    g_s_ring [2*BATCH*NHID];   // b-major [slot][b][h]
__device__ float    g_s_ringT[2*NHID*BATCH];   // k-major [slot][h][b]
__device__ unsigned g_cnt1[8];
__device__ unsigned g_cnt2 = 0;
__device__ unsigned g_gen  = 0;

typedef unsigned long long u64;

__device__ __forceinline__ void ffma2(u64& d, u64 a, u64 b) {
  asm("fma.rn.f32x2 %0, %1, %2, %0;" : "+l"(d) : "l"(a), "l"(b));
}
__device__ __forceinline__ u64 add2(u64 a, u64 b) {
  u64 r; asm("add.rn.f32x2 %0, %1, %2;" : "=l"(r) : "l"(a), "l"(b)); return r;
}
__device__ __forceinline__ u64 bcast2(float s) {
  u64 r; asm("mov.b64 %0, {%1, %1};" : "=l"(r) : "f"(s)); return r;
}
__device__ __forceinline__ float2 unpack2(u64 p) {
  float2 f; asm("mov.b64 {%0, %1}, %2;" : "=f"(f.x), "=f"(f.y) : "l"(p)); return f;
}
__device__ __forceinline__ u64 pack2(float lo, float hi) {
  u64 r; asm("mov.b64 %0, {%1, %2};" : "=l"(r) : "f"(lo), "f"(hi)); return r;
}

// tree grid barrier: 8 group counters -> root counter -> generation bump
__device__ __forceinline__ void grid_barrier(int blk) {
  __syncthreads();
  if (threadIdx.x == 0) {
    asm volatile("fence.acq_rel.gpu;" ::: "memory");   // release s stores
    unsigned my = *((volatile unsigned*)&g_gen);
    unsigned o1 = atomicAdd(&g_cnt1[blk & 7], 1u);
    if (o1 == 15u) {
      atomicExch(&g_cnt1[blk & 7], 0u);
      unsigned o2 = atomicAdd(&g_cnt2, 1u);
      if (o2 == 7u) {
        atomicExch(&g_cnt2, 0u);
        asm volatile("fence.acq_rel.gpu;" ::: "memory");
        atomicExch(&g_gen, my + 1u);
      }
    }
    while (*((volatile unsigned*)&g_gen) == my) { }
    asm volatile("fence.acq_rel.gpu;" ::: "memory");   // acquire
  }
  __syncthreads();
}

__global__ void __launch_bounds__(NTHR, 1)
bnn_kernel(const float* __restrict__ x,     // [T, B, NIN]
           const float* __restrict__ W_in,  // [NHID, NIN]
           const float* __restrict__ b_in,  // [NHID]
           const float* __restrict__ W_rec, // [NHID, NHID]
           const float* __restrict__ W_out, // [NOUT, NHID]
           const float* __restrict__ b_out, // [NOUT]
           float* __restrict__ out)         // [T, B, NOUT]
{
  extern __shared__ float sm[];
  float* ss = sm + OFF_SS;              // [k=640][20]: s (0-511) + x (512-639), k-major
  float* sb = sm + OFF_SB;              // [b=16][520]: s b-major (readout)
  u64*   st = (u64*)(sm + OFF_ST);      // [var=4][512]: neuron state, u64 per (h,ks)

  const int tid = threadIdx.x;
  const int blk = blockIdx.x;
  const int btile = blk >> 3;           // 16 b-tiles
  const int htile = blk & 7;            // 8  h-tiles
  const int b0 = btile * BT;
  const int h0 = htile * HT;

  // ---- GEMM mapping: warp = 4h x 8ks; thread owns 1 h, 16 b, 80 k (k=8r+ks) ----
  const int warp = tid >> 5;
  const int lane = tid & 31;
  const int hl = lane >> 3;             // 0..3
  const int ks = lane & 7;              // 0..7
  const int h  = warp * 4 + hl;         // 0..63

  // ---- prologue: weights into registers (once for all 1000 steps) ----
  float wreg[80];
  {
    const float* wr = W_rec + (size_t)(h0 + h)*NHID + ks;
    const float* wi = W_in  + (size_t)(h0 + h)*NIN  + ks;
    #pragma unroll
    for (int r = 0; r < 64; ++r) wreg[r] = __ldg(wr + 8*r);
    #pragma unroll
    for (int r = 0; r < 16; ++r) wreg[64 + r] = __ldg(wi + 8*r);
  }

  // zero s region of ss + neuron state; stage x[0]
  for (int i = tid; i < NHID*SS_STRIDE; i += NTHR) ss[i] = 0.f;
  for (int i = tid; i < 4*512*2; i += NTHR) sm[OFF_ST + i] = 0.f;
  {
    #pragma unroll
    for (int j = 0; j < 4; ++j) {
      int g = j*NTHR + tid;             // 0..2047
      int c = g & 127, bl = g >> 7;
      ss[(NHID + c)*SS_STRIDE + bl] = __ldg(x + (size_t)(b0 + bl)*NIN + c);
    }
  }
  __syncthreads();

  const float binh = __ldg(b_in + h0 + h);
  const int sidx = h*8 + ks;            // state index (owned, fixed)

  // readout mapping: warp = b row; lanes: 16 o x 2 kh
  const int ob = warp;
  const int o  = htile*16 + (lane & 15);
  const int kh = lane >> 4;
  const float bo = __ldg(b_out + o);
  const ulonglong2* wo2 = (const ulonglong2*)(W_out + (size_t)o*NHID);

  for (int t = 0; t < T_STEPS; ++t) {
    // ---- GEMM: y[h][16b] partial over this lane's 80 k ----
    u64 acc[8] = {0,0,0,0,0,0,0,0};
    {
      const ulonglong2* p = (const ulonglong2*)ss + (size_t)ks*5;
      #pragma unroll
      for (int r = 0; r < 80; ++r) {
        const ulonglong2* q = p + (size_t)r*40;   // (8r)*5
        ulonglong2 sA = q[0], sB = q[1], sC = q[2], sD = q[3];
        u64 wb = bcast2(wreg[r]);
        ffma2(acc[0], sA.x, wb); ffma2(acc[1], sA.y, wb);
        ffma2(acc[2], sB.x, wb); ffma2(acc[3], sB.y, wb);
        ffma2(acc[4], sC.x, wb); ffma2(acc[5], sC.y, wb);
        ffma2(acc[6], sD.x, wb); ffma2(acc[7], sD.y, wb);
      }
    }
    // ---- reduce-scatter over ks (lane bits 0-2): lane ends with b-pair 2ks ----
    const bool k2 = (ks & 4) != 0, k1 = (ks & 2) != 0, k0b = (ks & 1) != 0;
    u64 t4[4], t2[2], yu;
    #pragma unroll
    for (int j = 0; j < 4; ++j) {
      u64 snd = k2 ? acc[j] : acc[4 + j];
      u64 rcv = __shfl_xor_sync(0xffffffffu, snd, 4);
      t4[j] = add2(k2 ? acc[4 + j] : acc[j], rcv);
    }
    #pragma unroll
    for (int j = 0; j < 2; ++j) {
      u64 snd = k1 ? t4[j] : t4[2 + j];
      u64 rcv = __shfl_xor_sync(0xffffffffu, snd, 2);
      t2[j] = add2(k1 ? t4[2 + j] : t4[j], rcv);
    }
    {
      u64 snd = k0b ? t2[0] : t2[1];
      u64 rcv = __shfl_xor_sync(0xffffffffu, snd, 1);
      yu = add2(k0b ? t2[1] : t2[0], rcv);
    }

    // ---- GLIFR update for (h, b=2ks, 2ks+1); state in smem ----
    {
      float2 yy = unpack2(yu);
      float2 v  = unpack2(st[0*512 + sidx]);
      float2 a0 = unpack2(st[1*512 + sidx]);
      float2 a1 = unpack2(st[2*512 + sidx]);
      float2 sp = unpack2(st[3*512 + sidx]);
      #define UPD(i) { \
        float y  = 0.5f*(yy.i + binh); \
        a0.i = fmaf(a0.i,  0.85f, -0.05f*sp.i); \
        a1.i = fmaf(a1.i, -0.5f,  -0.05f*sp.i); \
        float it = y + a0.i + a1.i + 700.0f; \
        v.i  = v.i*0.99f*(1.0f - 0.05f*sp.i) + 0.00101953125f*it; \
        sp.i = 20.0f / (1.0f + __expf(-v.i*0.02f)); }
      UPD(x); UPD(y);
      #undef UPD
      st[0*512 + sidx] = pack2(v.x, v.y);
      st[1*512 + sidx] = pack2(a0.x, a0.y);
      st[2*512 + sidx] = pack2(a1.x, a1.y);
      st[3*512 + sidx] = pack2(sp.x, sp.y);

      // publish s[t]
      const int slot = t & 1;
      const int gb = b0 + 2*ks, gh = h0 + h;
      float* rg = g_s_ring  + (size_t)slot*BATCH*NHID;
      float* rT = g_s_ringT + (size_t)slot*NHID*BATCH;
      __stcg(rg + (size_t)gb*NHID + gh, sp.x);
      __stcg(rg + (size_t)(gb + 1)*NHID + gh, sp.y);
      __stcg((float2*)(rT + (size_t)gh*BATCH + gb), make_float2(sp.x, sp.y));
    }

    grid_barrier(blk);
    const int slot = t & 1;

    // ---- restage: ss <- rT (k-major), sb <- ring (b-major), x[t+1] ----
    {
      const float4* rT4 = (const float4*)(g_s_ringT + (size_t)slot*NHID*BATCH);
      #pragma unroll
      for (int j = 0; j < 4; ++j) {
        int g = j*NTHR + tid;           // 0..2047
        int k = g >> 2, bq = g & 3;
        float4 vv = __ldcg(rT4 + (size_t)k*(BATCH/4) + (b0 >> 2) + bq);
        *(float4*)(ss + k*SS_STRIDE + bq*4) = vv;
      }
      const float4* rg4 = (const float4*)(g_s_ring + (size_t)slot*BATCH*NHID);
      #pragma unroll
      for (int j = 0; j < 4; ++j) {
        int g = j*NTHR + tid;
        int r = g >> 7, c = g & 127;
        float4 vv = __ldcg(rg4 + (size_t)(b0 + r)*(NHID/4) + c);
        *(float4*)(sb + r*SB_STRIDE + c*4) = vv;
      }
      int tn = (t + 1 < T_STEPS) ? t + 1 : t;
      const float* xr = x + (size_t)tn*BATCH*NIN;
      #pragma unroll
      for (int j = 0; j < 4; ++j) {
        int g = j*NTHR + tid;
        int c = g & 127, bl = g >> 7;
        ss[(NHID + c)*SS_STRIDE + bl] = __ldg(xr + (size_t)(b0 + bl)*NIN + c);
      }
    }
    __syncthreads();

    // ---- readout: out[t][b][o] = s[t] @ W_out^T + b_out (from sb, f32x2) ----
    {
      const ulonglong2* sb2 = (const ulonglong2*)(sb + ob*SB_STRIDE);
      u64 A = 0, Bc = 0;
      #pragma unroll 8
      for (int i = 0; i < 64; ++i) {
        int k4 = i*2 + kh;
        ulonglong2 sv = sb2[k4];
        ulonglong2 wv = __ldg(wo2 + k4);
        ffma2(A, sv.x, wv.x); ffma2(Bc, sv.y, wv.y);
      }
      float2 fa = unpack2(A), fb = unpack2(Bc);
      float r = (fa.x + fa.y) + (fb.x + fb.y);
      r += __shfl_xor_sync(0xffffffffu, r, 16);
      if (kh == 0)
        out[(size_t)t*BATCH*NOUT + (size_t)(b0 + ob)*NOUT + o] = r + bo;
    }
    // next GEMM reads ss written above (synced); next restage write to sb is
    // gated by grid_barrier's entry __syncthreads -> readout reads are safe.
  }
}

extern "C" void kernel_launch(void* const* d_in, const int* in_sizes, int n_in,
                              void* d_out, int out_size) {
  const float* x     = (const float*)d_in[0];
  const float* W_in  = (const float*)d_in[1];
  const float* b_in  = (const float*)d_in[2];
  const float* W_rec = (const float*)d_in[3];
  const float* W_out = (const float*)d_in[4];
  const float* b_out = (const float*)d_in[5];
  float* out = (float*)d_out;

  cudaFuncSetAttribute(bnn_kernel,
                       cudaFuncAttributeMaxDynamicSharedMemorySize, SMEM_BYTES);
  bnn_kernel<<<NBLK, NTHR, SMEM_BYTES>>>(x, W_in, b_in, W_rec, W_out, b_out, out);
}

// round 6
// speedup vs baseline: 4.3841x; 3.2588x over previous
#include <cuda_runtime.h>
#include <cstdint>

#define T_STEPS 1000
#define BATCH   256
#define NIN     128
#define NHID    512
#define NOUT    128

#define NBLK 128
#define NTHR 512
#define BT 16      // batch rows per CTA
#define HT 64      // hidden cols per CTA
#define KTOT 640   // 512 recurrent + 128 input

#define WST 68     // wu float-stride per k row (64 + 4 pad; ksl*68 % 32 = 4*ksl -> conflict-free)
#define SST 20     // ss float-stride per k row (16 + 4 pad; ksl*20 % 32 pattern conflict-free)

#define OFF_WU 0
#define OFF_SS (KTOT*WST)                 // 43520 floats
#define SMEM_FLOATS (OFF_SS + KTOT*SST)   // 56320 floats
#define SMEM_BYTES (SMEM_FLOATS*4)        // 225280 B  (< 232448 max)

// L2-resident state rings (2 slots), accessed only via .cg
__device__ float    g_s_ring [2*BATCH*NHID];   // b-major [slot][b][h]
__device__ float    g_s_ringT[2*NHID*BATCH];   // k-major [slot][h][b]
__device__ unsigned g_cnt1[8];
__device__ unsigned g_cnt2 = 0;
__device__ unsigned g_gen  = 0;

typedef unsigned long long u64;

__device__ __forceinline__ void ffma2(u64& d, u64 a, u64 b) {
  asm("fma.rn.f32x2 %0, %1, %2, %0;" : "+l"(d) : "l"(a), "l"(b));
}
__device__ __forceinline__ u64 add2(u64 a, u64 b) {
  u64 r; asm("add.rn.f32x2 %0, %1, %2;" : "=l"(r) : "l"(a), "l"(b)); return r;
}
__device__ __forceinline__ u64 bcast2(float s) {
  u64 r; asm("mov.b64 %0, {%1, %1};" : "=l"(r) : "f"(s)); return r;
}
__device__ __forceinline__ u64 pack2(float lo, float hi) {
  u64 r; asm("mov.b64 %0, {%1, %2};" : "=l"(r) : "f"(lo), "f"(hi)); return r;
}
__device__ __forceinline__ float2 unpack2(u64 p) {
  float2 f; asm("mov.b64 {%0, %1}, %2;" : "=f"(f.x), "=f"(f.y) : "l"(p)); return f;
}

// tree grid barrier: 8 group counters -> root -> generation bump
__device__ __forceinline__ void grid_barrier(int blk) {
  __syncthreads();
  if (threadIdx.x == 0) {
    asm volatile("fence.acq_rel.gpu;" ::: "memory");
    unsigned my = *((volatile unsigned*)&g_gen);
    unsigned o1 = atomicAdd(&g_cnt1[blk & 7], 1u);
    if (o1 == 15u) {
      atomicExch(&g_cnt1[blk & 7], 0u);
      unsigned o2 = atomicAdd(&g_cnt2, 1u);
      if (o2 == 7u) {
        atomicExch(&g_cnt2, 0u);
        asm volatile("fence.acq_rel.gpu;" ::: "memory");
        atomicExch(&g_gen, my + 1u);
      }
    }
    while (*((volatile unsigned*)&g_gen) == my) { }
    asm volatile("fence.acq_rel.gpu;" ::: "memory");
  }
  __syncthreads();
}

__global__ void __launch_bounds__(NTHR, 1)
bnn_kernel(const float* __restrict__ x,     // [T, B, NIN]
           const float* __restrict__ W_in,  // [NHID, NIN]
           const float* __restrict__ b_in,  // [NHID]
           const float* __restrict__ W_rec, // [NHID, NHID]
           const float* __restrict__ W_out, // [NOUT, NHID]
           const float* __restrict__ b_out, // [NOUT]
           float* __restrict__ out)         // [T, B, NOUT]
{
  extern __shared__ float sm[];
  float* wu = sm + OFF_WU;   // [k=640][68]: wu[k][hl] = W[h0+hl][k] (rec+in unified)
  float* ss = sm + OFF_SS;   // [k=640][20]: s (rows 0-511) + x (rows 512-639), k-major

  const int tid = threadIdx.x;
  const int blk = blockIdx.x;
  const int btile = blk >> 3;           // 16 b-tiles
  const int htile = blk & 7;            // 8  h-tiles
  const int b0 = btile * BT;
  const int h0 = htile * HT;

  // ---- prologue: weights into SMEM k-major ----
  for (int i = tid; i < NHID*HT; i += NTHR) {
    int hl = i >> 9, k = i & 511;
    wu[k*WST + hl] = W_rec[(size_t)(h0 + hl)*NHID + k];
  }
  for (int i = tid; i < NIN*HT; i += NTHR) {
    int hl = i >> 7, k = i & 127;
    wu[(NHID + k)*WST + hl] = W_in[(size_t)(h0 + hl)*NIN + k];
  }
  // zero s region; stage x[0]
  for (int i = tid; i < NHID*(SST/4); i += NTHR)
    ((float4*)ss)[i] = make_float4(0.f, 0.f, 0.f, 0.f);
  __syncthreads();
  #pragma unroll
  for (int j = 0; j < 4; ++j) {
    int g = j*NTHR + tid;
    int c = g & 127, bl = g >> 7;
    ss[(NHID + c)*SST + bl] = __ldg(x + (size_t)(b0 + bl)*NIN + c);
  }
  __syncthreads();

  // ---- mapping: warp = bh(1)|ho(3); lane = ksl (32-way k-split) ----
  const int warp = tid >> 5;
  const int lane = tid & 31;
  const int bh = warp >> 3;             // 0/1: b-half (8 b)
  const int ho = warp & 7;              // 0..7: h-oct (8 h)
  const int ksl = lane;                 // k = ksl + 32r

  const float4*     sp4 = (const float4*)ss + ksl*(SST/4) + bh*2;
  const ulonglong2* wp2 = (const ulonglong2*)wu + ksl*(WST/4) + ho*2;

  // update ownership (post reduce-scatter): b = b0+bh*8+(lane>>2), h-pair at ho*8+(lane&3)*2
  const int ub = b0 + bh*8 + (lane >> 2);
  const int uh = h0 + ho*8 + (lane & 3)*2;
  const float2 bin = *(const float2*)(b_in + uh);

  // readout: warp covers o_e = htile*16+ho*2, o_o = +1; writer lanes (lane&3)==0
  const float* wo0 = W_out + (size_t)(htile*16 + ho*2) * NHID + ksl;
  const float* wo1 = wo0 + NHID;
  const int widx = lane >> 2;                   // 0..7 = bp*2+op
  const int wb   = b0 + bh*8 + (widx >> 1)*2;   // output b (pair start)
  const int wo_  = htile*16 + ho*2 + (widx & 1);
  const float bo = __ldg(b_out + wo_);

  float2 v  = make_float2(0.f, 0.f);
  float2 a0 = make_float2(0.f, 0.f);
  float2 a1 = make_float2(0.f, 0.f);
  float2 sp = make_float2(0.f, 0.f);

  for (int t = 0; t <= T_STEPS; ++t) {
    // ---- GEMM over ss (= s[t-1], x[t]) + fused readout partials (out[t-1]) ----
    u64 acc[32];                         // idx = bl*4 + hp  (bl 0..7, hp 0..3)
    #pragma unroll
    for (int i = 0; i < 32; ++i) acc[i] = 0;
    u64 racc[8] = {0,0,0,0,0,0,0,0};     // idx = bp*2 + op

    #pragma unroll
    for (int r = 0; r < 20; ++r) {
      float4     sa = sp4[r*160];        // b0..b3 of this k
      float4     sb = sp4[r*160 + 1];    // b4..b7
      ulonglong2 wA = wp2[r*544];        // h-pairs 0,1
      ulonglong2 wB = wp2[r*544 + 1];    // h-pairs 2,3
      u64 s0 = bcast2(sa.x), s1 = bcast2(sa.y), s2 = bcast2(sa.z), s3 = bcast2(sa.w);
      u64 s4 = bcast2(sb.x), s5 = bcast2(sb.y), s6 = bcast2(sb.z), s7 = bcast2(sb.w);
      ffma2(acc[ 0], s0, wA.x); ffma2(acc[ 1], s0, wA.y); ffma2(acc[ 2], s0, wB.x); ffma2(acc[ 3], s0, wB.y);
      ffma2(acc[ 4], s1, wA.x); ffma2(acc[ 5], s1, wA.y); ffma2(acc[ 6], s1, wB.x); ffma2(acc[ 7], s1, wB.y);
      ffma2(acc[ 8], s2, wA.x); ffma2(acc[ 9], s2, wA.y); ffma2(acc[10], s2, wB.x); ffma2(acc[11], s2, wB.y);
      ffma2(acc[12], s3, wA.x); ffma2(acc[13], s3, wA.y); ffma2(acc[14], s3, wB.x); ffma2(acc[15], s3, wB.y);
      ffma2(acc[16], s4, wA.x); ffma2(acc[17], s4, wA.y); ffma2(acc[18], s4, wB.x); ffma2(acc[19], s4, wB.y);
      ffma2(acc[20], s5, wA.x); ffma2(acc[21], s5, wA.y); ffma2(acc[22], s5, wB.x); ffma2(acc[23], s5, wB.y);
      ffma2(acc[24], s6, wA.x); ffma2(acc[25], s6, wA.y); ffma2(acc[26], s6, wB.x); ffma2(acc[27], s6, wB.y);
      ffma2(acc[28], s7, wA.x); ffma2(acc[29], s7, wA.y); ffma2(acc[30], s7, wB.x); ffma2(acc[31], s7, wB.y);
      if (r < 16) {                      // s-region only (k < 512)
        u64 w0b = bcast2(__ldcg(wo0 + 32*r));
        u64 w1b = bcast2(__ldcg(wo1 + 32*r));
        u64 p0 = pack2(sa.x, sa.y), p1 = pack2(sa.z, sa.w);
        u64 p2 = pack2(sb.x, sb.y), p3 = pack2(sb.z, sb.w);
        ffma2(racc[0], p0, w0b); ffma2(racc[1], p0, w1b);
        ffma2(racc[2], p1, w0b); ffma2(racc[3], p1, w1b);
        ffma2(racc[4], p2, w0b); ffma2(racc[5], p2, w1b);
        ffma2(racc[6], p3, w0b); ffma2(racc[7], p3, w1b);
      }
    }

    // ---- in-warp reduce-scatter of acc (lane ends with full sum of acc[lane]) ----
    #pragma unroll
    for (int m = 16; m >= 1; m >>= 1) {
      bool hi = (lane & m) != 0;
      #pragma unroll
      for (int j = 0; j < m; ++j) {
        u64 snd = hi ? acc[j] : acc[m + j];
        u64 rcv = __shfl_xor_sync(0xffffffffu, snd, m);
        acc[j] = add2(hi ? acc[m + j] : acc[j], rcv);
      }
    }
    // acc[0] = y-partial-sum for (b = ub, h-pair = uh)

    // ---- readout reduce: scatter over lane bits 4..2, then sum bits 1..0 ----
    #pragma unroll
    for (int m = 16; m >= 4; m >>= 1) {
      bool hi = (lane & m) != 0;
      int half = m >> 2;                 // racc block half: 4, 2, 1
      #pragma unroll
      for (int j = 0; j < 4; ++j) {      // upper bound; only j < half active
        if (j < half) {
          u64 snd = hi ? racc[j] : racc[half + j];
          u64 rcv = __shfl_xor_sync(0xffffffffu, snd, m);
          racc[j] = add2(hi ? racc[half + j] : racc[j], rcv);
        }
      }
    }
    racc[0] = add2(racc[0], __shfl_xor_sync(0xffffffffu, racc[0], 2));
    racc[0] = add2(racc[0], __shfl_xor_sync(0xffffffffu, racc[0], 1));
    if (t >= 1 && (lane & 3) == 0) {
      float2 rv = unpack2(racc[0]);
      float* op = out + (size_t)(t - 1)*BATCH*NOUT + (size_t)wb*NOUT + wo_;
      op[0]    = rv.x + bo;
      op[NOUT] = rv.y + bo;
    }

    if (t < T_STEPS) {
      // ---- GLIFR update for (ub, uh..uh+1) ----
      float2 yy = unpack2(acc[0]);
      #define UPD(i) { \
        float y  = 0.5f*(yy.i + bin.i); \
        a0.i = fmaf(a0.i,  0.85f, -0.05f*sp.i); \
        a1.i = fmaf(a1.i, -0.5f,  -0.05f*sp.i); \
        float it = y + a0.i + a1.i + 700.0f; \
        v.i  = v.i*0.99f*(1.0f - 0.05f*sp.i) + 0.00101953125f*it; \
        sp.i = 20.0f / (1.0f + __expf(-v.i*0.02f)); }
      UPD(x); UPD(y);
      #undef UPD

      // publish s[t]
      const int slot = t & 1;
      float* rg = g_s_ring  + (size_t)slot*BATCH*NHID;
      float* rT = g_s_ringT + (size_t)slot*NHID*BATCH;
      __stcg((float2*)(rg + (size_t)ub*NHID + uh), sp);
      __stcg(rT + (size_t)uh*BATCH + ub, sp.x);
      __stcg(rT + (size_t)(uh + 1)*BATCH + ub, sp.y);

      grid_barrier(blk);

      // ---- restage: ss s-part <- ringT; x[t+1] -> x-part ----
      {
        const float4* rT4 = (const float4*)(g_s_ringT + (size_t)slot*NHID*BATCH);
        #pragma unroll
        for (int j = 0; j < 4; ++j) {
          int g = j*NTHR + tid;
          int k = g & 511, bq = g >> 9;
          float4 vv = __ldcg(rT4 + (size_t)k*(BATCH/4) + (b0 >> 2) + bq);
          *(float4*)(ss + k*SST + bq*4) = vv;
        }
        int tn = (t + 1 < T_STEPS) ? t + 1 : (T_STEPS - 1);
        const float* xr = x + (size_t)tn*BATCH*NIN;
        #pragma unroll
        for (int j = 0; j < 4; ++j) {
          int g = j*NTHR + tid;
          int c = g & 127, bl = g >> 7;
          ss[(NHID + c)*SST + bl] = __ldg(xr + (size_t)(b0 + bl)*NIN + c);
        }
      }
      __syncthreads();
    }
  }
}

extern "C" void kernel_launch(void* const* d_in, const int* in_sizes, int n_in,
                              void* d_out, int out_size) {
  const float* x     = (const float*)d_in[0];
  const float* W_in  = (const float*)d_in[1];
  const float* b_in  = (const float*)d_in[2];
  const float* W_rec = (const float*)d_in[3];
  const float* W_out = (const float*)d_in[4];
  const float* b_out = (const float*)d_in[5];
  float* out = (float*)d_out;

  cudaFuncSetAttribute(bnn_kernel,
                       cudaFuncAttributeMaxDynamicSharedMemorySize, SMEM_BYTES);
  bnn_kernel<<<NBLK, NTHR, SMEM_BYTES>>>(x, W_in, b_in, W_rec, W_out, b_out, out);
}